// round 15
// baseline (speedup 1.0000x reference)
#include <cuda_runtime.h>
#include <cuda_fp16.h>

#define E   300
#define P   5
#define H   200
#define S   256
#define L   34
#define B   8
#define KPP 160          // k-word-pairs per A row (K = 320 padded)
#define NP  704          // N padded (702 -> 704)
#define M   (B*S)        // 2048
#define FCK (3*E + 2*H)  // 1300

// ---------------- scratch ----------------
__device__ __align__(16) unsigned d_Ahp[M*KPP];   // A hi plane, fp16x2 [row][kpair]
__device__ __align__(16) unsigned d_Alp[M*KPP];   // A lo plane ((x-hi)*1024)
__device__ __align__(16) unsigned d_Whp[KPP*NP];  // W plane, fp16x2 [kpair][n]
__device__ __align__(16) float d_Y[M*NP];
__device__ __align__(16) float d_g4[50*2048];     // [cquad][plane][q][4ch]
__device__ __align__(16) float d_gB0[S*H];        // [i][h]
__device__ __align__(16) float d_gB255[S*H];      // [i][h]
__device__ __align__(16) float d_poolA[M*2*H];    // zone-0 partial (relu'd)
__device__ __align__(16) float d_poolB[M*2*H];    // zone-1 partial (relu'd)
__device__ __align__(16) float d_fcW2t[L*400];    // [l][c]
__device__ __align__(16) float4 d_fcW4[100*34];   // [cquad][l] = W[l][4q..4q+3]

// ---------------- helpers ----------------
union F2U { float2 f; unsigned long long u; };
__device__ __forceinline__ float2 add2(float2 a, float2 b) {
    F2U ua, ub, uc;
    ua.f = a; ub.f = b;
    asm("add.rn.f32x2 %0, %1, %2;" : "=l"(uc.u) : "l"(ua.u), "l"(ub.u));
    return uc.f;
}
__device__ __forceinline__ float4 add44(float4 a, float4 b) {
    float2 lo = add2(make_float2(a.x, a.y), make_float2(b.x, b.y));
    float2 hi = add2(make_float2(a.z, a.w), make_float2(b.z, b.w));
    return make_float4(lo.x, lo.y, hi.x, hi.y);
}
__device__ __forceinline__ float4 max44(float4 a, float4 b) {
    return make_float4(fmaxf(a.x, b.x), fmaxf(a.y, b.y), fmaxf(a.z, b.z), fmaxf(a.w, b.w));
}
__device__ __forceinline__ unsigned pk2h(float a, float b) {
    __half2 t = __floats2half2_rn(a, b);
    return *reinterpret_cast<unsigned*>(&t);
}
__device__ __forceinline__ void mma_fp16(float* d, const unsigned* a, const unsigned* b) {
    asm volatile("mma.sync.aligned.m16n8k16.row.col.f32.f16.f16.f32 "
        "{%0,%1,%2,%3},{%4,%5,%6,%7},{%8,%9},{%0,%1,%2,%3};\n"
        : "+f"(d[0]), "+f"(d[1]), "+f"(d[2]), "+f"(d[3])
        : "r"(a[0]), "r"(a[1]), "r"(a[2]), "r"(a[3]), "r"(b[0]), "r"(b[1]));
}
__device__ __forceinline__ void cpa16(unsigned dst, const void* src) {
    asm volatile("cp.async.ca.shared.global [%0], [%1], 16;\n" :: "r"(dst), "l"(src));
}

// ---------------- fused prep: gather + W plane + fcW tables + g-tables ----------------
__device__ __forceinline__ float wallv(int e, int c, const float* conv_W, const float* fc_W) {
    if (e >= E) return 0.0f;
    if (c < 600) {
        int k = c / 200, h = c % 200;
        return conv_W[h*((E+P)*3) + e*3 + k];
    }
    if (c < 702) {
        int cc = c - 600, k = cc / L, l = cc % L;
        return fc_W[l*FCK + 2*H + k*E + e];
    }
    return 0.0f;
}

__global__ __launch_bounds__(256) void prep_kernel(const int* in32, const float* word_emb,
                                                   const float* conv_W, const float* fc_W,
                                                   const float* pf_emb) {
    int blk = blockIdx.x;
    int tid = threadIdx.x;
    if (blk < 2048) {                              // gather embeddings, fp16 hi/lo planes
        int row = blk;
        int lane = tid & 31;
        int hw = in32[2*lane + 1];
        unsigned nz = __ballot_sync(0xffffffffu, hw != 0);
        long long tok = (nz == 0) ? ((const long long*)in32)[row]
                                  : (long long)in32[row];
        int p = tid;
        if (p >= KPP) return;
        const float* src = word_emb + tok * E;
        float x0 = 0.0f, x1 = 0.0f;
        int e = 2*p;
        if (e < E) {
            x0 = src[e];
            x1 = (e + 1 < E) ? src[e+1] : 0.0f;
        }
        float h0 = __half2float(__float2half_rn(x0));
        float h1 = __half2float(__float2half_rn(x1));
        d_Ahp[row*KPP + p] = pk2h(h0, h1);
        d_Alp[row*KPP + p] = pk2h((x0 - h0) * 1024.0f, (x1 - h1) * 1024.0f);
        return;
    }
    if (blk < 2208) {                              // W plane, kpair = blk-2048
        int kp = blk - 2048;
        for (int c = tid; c < NP; c += 256) {
            float v0 = wallv(2*kp,     c, conv_W, fc_W);
            float v1 = wallv(2*kp + 1, c, conv_W, fc_W);
            d_Whp[kp*NP + c] = pk2h(v0, v1);
        }
        return;
    }
    if (blk == 2208) {                             // fcW2t[l][c] + fcW4[q][l]
        for (int idx = tid; idx < L*400; idx += 256) {
            int l = idx / 400, c = idx % 400;
            d_fcW2t[idx] = fc_W[l*FCK + c];
        }
        for (int idx = tid; idx < 100*34; idx += 256) {
            int q = idx / 34, l = idx % 34;
            const float* wr = fc_W + l*FCK + 4*q;
            d_fcW4[idx] = make_float4(wr[0], wr[1], wr[2], wr[3]);
        }
        return;
    }
    int h = blk - 2209;                            // 0..199 g-tables
    float w0[P], w1[P], w2[P];
    #pragma unroll
    for (int p = 0; p < P; p++) {
        const float* wp = conv_W + h*(E+P)*3 + (E+p)*3;
        w0[p] = wp[0]; w1[p] = wp[1]; w2[p] = wp[2];
    }
    for (int dd = tid; dd < 512; dd += 256) {
        int d = dd - 256;
        int i0 = abs(d-1); if (i0 > 255) i0 = 255;
        int i1 = abs(d);   if (i1 > 255) i1 = 255;
        int i2 = abs(d+1); if (i2 > 255) i2 = 255;
        float acc = 0.0f;
        #pragma unroll
        for (int p = 0; p < P; p++)
            acc += w0[p]*pf_emb[i0*P+p] + w1[p]*pf_emb[i1*P+p] + w2[p]*pf_emb[i2*P+p];
        d_g4[(h>>2)*2048 + (dd&3)*512 + (dd>>2)*4 + (h&3)] = acc;
    }
    if (tid >= 1 && tid <= 254) {
        int i = tid;
        float a0 = 0.0f, a255 = 0.0f;
        #pragma unroll
        for (int p = 0; p < P; p++) {
            a0   += w1[p]*pf_emb[i*P+p] + w2[p]*pf_emb[(i-1)*P+p];
            a255 += w0[p]*pf_emb[(254-i >= 0 ? 254-i : i-254)*P+p] + w1[p]*pf_emb[(255-i)*P+p];
        }
        d_gB0[i*H + h]   = a0;
        d_gB255[i*H + h] = a255;
    }
}

// ---------------- GEMM: 64x64 tiles, fp16 2-pass, cp.async double-buffered ----------------
__global__ __launch_bounds__(256) void gemm_kernel() {
    __shared__ unsigned Ah[2][64][20], Al[2][64][20];
    __shared__ unsigned Bs[2][16][72];

    const int t = threadIdx.x, lane = t & 31, warp = t >> 5;
    const int wm = warp >> 1, wn = warp & 1;
    const int mBase = wm * 16, nBase = wn * 32;
    const int r0 = lane >> 2, c0 = lane & 3;

    float acch[4][4], accl[4][4];
    #pragma unroll
    for (int ni = 0; ni < 4; ni++)
        #pragma unroll
        for (int q = 0; q < 4; q++) { acch[ni][q] = 0.0f; accl[ni][q] = 0.0f; }

    const unsigned* Agh = d_Ahp + (size_t)blockIdx.x * 64 * KPP;
    const unsigned* Agl = d_Alp + (size_t)blockIdx.x * 64 * KPP;
    const unsigned* Bg  = d_Whp + blockIdx.y * 64;

    const int am   = t >> 2;
    const int aseg = (t & 3) * 4;
    const int bk   = t >> 4;
    const int bn4  = (t & 15) * 4;

    unsigned sAh = (unsigned)__cvta_generic_to_shared(&Ah[0][am][aseg]);
    unsigned sAl = (unsigned)__cvta_generic_to_shared(&Al[0][am][aseg]);
    unsigned sB  = (unsigned)__cvta_generic_to_shared(&Bs[0][bk][bn4]);
    const unsigned A_ST = 64*20*4;
    const unsigned B_ST = 16*72*4;

    {
        cpa16(sAh, Agh + am*KPP + aseg);
        cpa16(sAl, Agl + am*KPP + aseg);
        cpa16(sB,  Bg + bk*NP + bn4);
        asm volatile("cp.async.commit_group;\n");
    }

    #pragma unroll 1
    for (int ch = 0; ch < 10; ch++) {
        int st = ch & 1;
        if (ch < 9) {
            int kc = (ch + 1) * 16;
            int st1 = st ^ 1;
            cpa16(sAh + st1*A_ST, Agh + am*KPP + kc + aseg);
            cpa16(sAl + st1*A_ST, Agl + am*KPP + kc + aseg);
            cpa16(sB  + st1*B_ST, Bg + (kc + bk)*NP + bn4);
            asm volatile("cp.async.commit_group;\n");
            asm volatile("cp.async.wait_group 1;\n");
        } else {
            asm volatile("cp.async.wait_group 0;\n");
        }
        __syncthreads();

        #pragma unroll
        for (int ks = 0; ks < 2; ks++) {
            int p0 = ks*8 + c0;
            int mr = mBase + r0;
            unsigned ah[4], al[4];
            ah[0] = Ah[st][mr][p0];     al[0] = Al[st][mr][p0];
            ah[1] = Ah[st][mr+8][p0];   al[1] = Al[st][mr+8][p0];
            ah[2] = Ah[st][mr][p0+4];   al[2] = Al[st][mr][p0+4];
            ah[3] = Ah[st][mr+8][p0+4]; al[3] = Al[st][mr+8][p0+4];
            unsigned bb[4][2];
            #pragma unroll
            for (int ni = 0; ni < 4; ni++) {
                int n = nBase + ni*8 + r0;
                bb[ni][0] = Bs[st][p0][n];
                bb[ni][1] = Bs[st][p0+4][n];
            }
            #pragma unroll
            for (int ni = 0; ni < 4; ni++) {
                mma_fp16(acch[ni], ah, bb[ni]);
                mma_fp16(accl[ni], al, bb[ni]);
            }
        }
        __syncthreads();
    }

    const float RS = 1.0f / 1024.0f;
    float* Yg = d_Y + (size_t)(blockIdx.x*64)*NP + blockIdx.y*64;
    int mr = mBase + r0;
    #pragma unroll
    for (int ni = 0; ni < 4; ni++) {
        int nc = nBase + ni*8 + 2*c0;
        *(float2*)(Yg + mr*NP + nc) =
            make_float2(fmaf(accl[ni][0], RS, acch[ni][0]), fmaf(accl[ni][1], RS, acch[ni][1]));
        *(float2*)(Yg + (mr+8)*NP + nc) =
            make_float2(fmaf(accl[ni][2], RS, acch[ni][2]), fmaf(accl[ni][3], RS, acch[ni][3]));
    }
}

// ---------------- fused ct + pooling: 2 centers x 4 ch/thread, 256 thr ----------------
__device__ __forceinline__ float4 compute_ct4(int b, int j, int cb, float4 v) {
    int row = b*S + j;
    v = add44(v, *(const float4*)&d_Y[row*NP + 200 + cb]);
    if (j > 0)   v = add44(v, *(const float4*)&d_Y[(row-1)*NP + cb]);
    if (j < S-1) v = add44(v, *(const float4*)&d_Y[(row+1)*NP + 400 + cb]);
    return v;
}

#define UPD2_MIX(cc, vA, vB, jj) do { \
    int t2_ = (jj) - 2*lt; \
    float4 x_; \
    x_ = add44(cc, vA); if (t2_ <= 0) mL[0] = max44(mL[0], x_); else mR[0] = max44(mR[0], x_); \
    x_ = add44(cc, vB); if (t2_ <= 1) mL[1] = max44(mL[1], x_); else mR[1] = max44(mR[1], x_); \
} while(0)

#define UPD2_UNI(cc, vA, vB) do { \
    mU[0] = max44(mU[0], add44(cc, vA)); \
    mU[1] = max44(mU[1], add44(cc, vB)); \
} while(0)

__global__ __launch_bounds__(256) void pool_kernel(const float* conv_b) {
    int bx = blockIdx.x;            // channel octet 0..24
    int b  = blockIdx.y;
    int z  = blockIdx.z;            // j-zone
    __shared__ float4 gp[2][4][128];   // [group][plane][q]
    __shared__ float4 cts[2][128];
    int t = threadIdx.x, g = t >> 7, lt = t & 127;
    int cb = bx*8 + g*4;

    const float4* gsrc = (const float4*)d_g4 + (bx*2 + g)*512;
    float4* gdst = &gp[g][0][0];
    #pragma unroll
    for (int r = 0; r < 4; r++)
        gdst[lt + 128*r] = gsrc[lt + 128*r];

    float4 cb4 = *(const float4*)&conv_b[cb];
    cts[g][lt] = compute_ct4(b, z*128 + lt, cb, cb4);
    __syncthreads();

    const int ifirst = 2*lt + 1;
    const float NEG = -1e30f;
    float4 neg4 = make_float4(NEG, NEG, NEG, NEG);
    float4 mL[2], mR[2];
    if (z == 0) {
        float4 c0 = cts[g][0];
        #pragma unroll
        for (int k = 0; k < 2; k++) {
            int ie = min(ifirst + k, 254);
            mL[k] = add44(c0, *(const float4*)&d_gB0[ie*H + cb]);
            mR[k] = neg4;
        }
    } else {
        float4 c255 = cts[g][127];
        #pragma unroll
        for (int k = 0; k < 2; k++) {
            int ie = min(ifirst + k, 254);
            mR[k] = add44(c255, *(const float4*)&d_gB255[ie*H + cb]);
            mL[k] = neg4;
        }
    }

    const int jstart = z ? 128 : 1;
    const float4* cz = &cts[g][0] - z*128;

#define GLD(dd) gp[g][(dd)&3][(dd)>>2]
    // window invariant: v_m = g(d0+m), d0 = j + 253 - 2lt; step s, center k uses v_{s+2-k}
    int d0 = jstart + 253 - 2*lt;
    float4 v1 = GLD(d0+1), v2 = GLD(d0+2), v3 = GLD(d0+3), v4 = GLD(d0+4), v5 = GLD(d0+5);

    int wq = (t >> 5) & 3;
    bool mixed = z ? (wq >= 2) : (wq < 2);
    int j = jstart;
    if (mixed) {
        #pragma unroll 2
        for (int blkI = 0; blkI < 31; blkI++, j += 4) {
            int dp = j + 259 - 2*lt;             // prefetch d0+6..d0+9
            float4 p0 = GLD(dp), p1 = GLD(dp+1), p2 = GLD(dp+2), p3 = GLD(dp+3);
            float4 c0 = cz[j], c1 = cz[j+1], c2 = cz[j+2], c3 = cz[j+3];
            UPD2_MIX(c0, v2, v1, j);
            UPD2_MIX(c1, v3, v2, j+1);
            UPD2_MIX(c2, v4, v3, j+2);
            UPD2_MIX(c3, v5, v4, j+3);
            v1 = v5; v2 = p0; v3 = p1; v4 = p2; v5 = p3;
        }
        float4 c0 = cz[j], c1 = cz[j+1], c2 = cz[j+2];
        UPD2_MIX(c0, v2, v1, j);
        UPD2_MIX(c1, v3, v2, j+1);
        UPD2_MIX(c2, v4, v3, j+2);
    } else {
        float4 mU[2];
        #pragma unroll
        for (int k = 0; k < 2; k++) mU[k] = z ? mR[k] : mL[k];
        #pragma unroll 2
        for (int blkI = 0; blkI < 31; blkI++, j += 4) {
            int dp = j + 259 - 2*lt;
            float4 p0 = GLD(dp), p1 = GLD(dp+1), p2 = GLD(dp+2), p3 = GLD(dp+3);
            float4 c0 = cz[j], c1 = cz[j+1], c2 = cz[j+2], c3 = cz[j+3];
            UPD2_UNI(c0, v2, v1);
            UPD2_UNI(c1, v3, v2);
            UPD2_UNI(c2, v4, v3);
            UPD2_UNI(c3, v5, v4);
            v1 = v5; v2 = p0; v3 = p1; v4 = p2; v5 = p3;
        }
        float4 c0 = cz[j], c1 = cz[j+1], c2 = cz[j+2];
        UPD2_UNI(c0, v2, v1);
        UPD2_UNI(c1, v3, v2);
        UPD2_UNI(c2, v4, v3);
        #pragma unroll
        for (int k = 0; k < 2; k++) { if (z) mR[k] = mU[k]; else mL[k] = mU[k]; }
    }
#undef GLD

    float4 z4 = make_float4(0.f, 0.f, 0.f, 0.f);
    float* dst = z ? d_poolB : d_poolA;
    #pragma unroll
    for (int k = 0; k < 2; k++) {
        int i = ifirst + k;
        if (i <= 254) {
            *(float4*)&dst[(b*S + i)*(2*H) + cb]     = max44(mL[k], z4);
            *(float4*)&dst[(b*S + i)*(2*H) + H + cb] = max44(mR[k], z4);
        }
    }
}

// ---------------- final logits: warp = 2 rows x quarter-q, W shared ----------------
__global__ __launch_bounds__(512) void final_kernel(const float* fc_b, float* out) {
    __shared__ float4 s_pm[8][100];     // 8 rows x 400 ch, relu'd pool maxes
    __shared__ float s_part[8][4][32];
    __shared__ float s_p32[8][4], s_p33[8][4];
    int tid = threadIdx.x;
    int gw0 = blockIdx.x * 8;

    const float4* pA = (const float4*)d_poolA + gw0*100;
    const float4* pB = (const float4*)d_poolB + gw0*100;
    #pragma unroll
    for (int it = 0; it < 2; it++) {
        int idx = tid + it*512;
        if (idx < 800)
            s_pm[idx/100][idx%100] = max44(pA[idx], pB[idx]);
    }
    __syncthreads();

    int w = tid >> 5, lane = tid & 31;
    int rp = w & 3, qq = w >> 2;        // rows 2rp,2rp+1 ; q-quarter qq
    int r0i = 2*rp, r1i = 2*rp + 1;
    const float4* Wq = d_fcW4 + lane;   // lane-major, L1-hot
    const float4* m0p = &s_pm[r0i][0];
    const float4* m1p = &s_pm[r1i][0];
    int qb = qq * 25;

    float a0 = 0.f, a1 = 0.f, b0 = 0.f, b1 = 0.f;
    #pragma unroll
    for (int u = 0; u < 5; u++) {
        int q = qb + u*5;
        // 5-wide batches: 15 independent loads in flight
        float4 w0 = Wq[(q+0)*34], w1 = Wq[(q+1)*34], w2 = Wq[(q+2)*34],
               w3 = Wq[(q+3)*34], w4 = Wq[(q+4)*34];
        float4 x0 = m0p[q+0], x1 = m0p[q+1], x2 = m0p[q+2], x3 = m0p[q+3], x4 = m0p[q+4];
        float4 y0 = m1p[q+0], y1 = m1p[q+1], y2 = m1p[q+2], y3 = m1p[q+3], y4 = m1p[q+4];
        a0 += x0.x*w0.x + x1.x*w1.x + x2.x*w2.x + x3.x*w3.x + x4.x*w4.x
            + x0.y*w0.y + x1.y*w1.y + x2.y*w2.y + x3.y*w3.y + x4.y*w4.y;
        a1 += x0.z*w0.z + x1.z*w1.z + x2.z*w2.z + x3.z*w3.z + x4.z*w4.z
            + x0.w*w0.w + x1.w*w1.w + x2.w*w2.w + x3.w*w3.w + x4.w*w4.w;
        b0 += y0.x*w0.x + y1.x*w1.x + y2.x*w2.x + y3.x*w3.x + y4.x*w4.x
            + y0.y*w0.y + y1.y*w1.y + y2.y*w2.y + y3.y*w3.y + y4.y*w4.y;
        b1 += y0.z*w0.z + y1.z*w1.z + y2.z*w2.z + y3.z*w3.z + y4.z*w4.z
            + y0.w*w0.w + y1.w*w1.w + y2.w*w2.w + y3.w*w3.w + y4.w*w4.w;
    }
    s_part[r0i][qq][lane] = a0 + a1;
    s_part[r1i][qq][lane] = b0 + b1;

    // l = 32, 33 partials over this warp's c-quarter, both rows
    const float* sm0 = (const float*)m0p;
    const float* sm1 = (const float*)m1p;
    const float* W32 = d_fcW2t + 32 * 400;
    const float* W33 = d_fcW2t + 33 * 400;
    float r32a = 0.f, r33a = 0.f, r32b = 0.f, r33b = 0.f;
    int cend = 100*qq + 100;
    for (int c = 100*qq + lane; c < cend; c += 32) {
        float wa = W32[c], wb = W33[c];
        float pa = sm0[c], pb = sm1[c];
        r32a += pa * wa; r33a += pa * wb;
        r32b += pb * wa; r33b += pb * wb;
    }
    #pragma unroll
    for (int off = 16; off > 0; off >>= 1) {
        r32a += __shfl_xor_sync(0xFFFFFFFF, r32a, off);
        r33a += __shfl_xor_sync(0xFFFFFFFF, r33a, off);
        r32b += __shfl_xor_sync(0xFFFFFFFF, r32b, off);
        r33b += __shfl_xor_sync(0xFFFFFFFF, r33b, off);
    }
    if (lane == 0) {
        s_p32[r0i][qq] = r32a; s_p33[r0i][qq] = r33a;
        s_p32[r1i][qq] = r32b; s_p33[r1i][qq] = r33b;
    }
    __syncthreads();

    if (w >= 8) return;
    int r = w;
    int gw = gw0 + r;
    int s = gw & (S-1);
    float* o = out + gw * L;
    if (s == 0 || s == S-1) {
        o[lane] = 0.0f;
        if (lane < 2) o[lane + 32] = (lane == 1) ? 1.0f : 0.0f;
        return;
    }
    float acc0 = s_part[r][0][lane] + s_part[r][1][lane]
               + s_part[r][2][lane] + s_part[r][3][lane] + fc_b[lane];
    acc0 += d_Y[(gw-1)*NP + 600 + lane]
          + d_Y[gw*NP     + 634 + lane]
          + d_Y[(gw+1)*NP + 668 + lane];
    o[lane] = acc0;

    if (lane < 2) {
        float rr = (lane == 0)
            ? (s_p32[r][0] + s_p32[r][1] + s_p32[r][2] + s_p32[r][3])
            : (s_p33[r][0] + s_p33[r][1] + s_p33[r][2] + s_p33[r][3]);
        rr += fc_b[32 + lane]
            + d_Y[(gw-1)*NP + 632 + lane]
            + d_Y[gw*NP     + 666 + lane]
            + d_Y[(gw+1)*NP + 700 + lane];
        o[32 + lane] = rr;
    }
}

extern "C" void kernel_launch(void* const* d_in, const int* in_sizes, int n_in,
                              void* d_out, int out_size) {
    const int*   inputs   = (const int*)d_in[0];
    const float* word_emb = (const float*)d_in[1];
    const float* pf_emb   = (const float*)d_in[2];
    const float* conv_W   = (const float*)d_in[3];
    const float* conv_b   = (const float*)d_in[4];
    const float* fc_W     = (const float*)d_in[5];
    const float* fc_b     = (const float*)d_in[6];
    float* out = (float*)d_out;

    prep_kernel<<<2409, 256>>>(inputs, word_emb, conv_W, fc_W, pf_emb);   // launch 0

    dim3 ggrid(M/64, NP/64);
    gemm_kernel<<<ggrid, 256>>>();                        // launch 1

    dim3 pgrid(25, B, 2);
    pool_kernel<<<pgrid, 256>>>(conv_b);                  // launch 2

    final_kernel<<<256, 512>>>(fc_b, out);                // launch 3 (profiled slot)
}

// round 16
// speedup vs baseline: 1.0370x; 1.0370x over previous
#include <cuda_runtime.h>
#include <cuda_fp16.h>

#define E   300
#define P   5
#define H   200
#define S   256
#define L   34
#define B   8
#define KPP 160          // k-word-pairs per A row (K = 320 padded)
#define NP  704          // N padded (702 -> 704)
#define M   (B*S)        // 2048
#define FCK (3*E + 2*H)  // 1300

// ---------------- scratch ----------------
__device__ __align__(16) unsigned d_Ahp[M*KPP];   // A hi plane, fp16x2 [row][kpair]
__device__ __align__(16) unsigned d_Alp[M*KPP];   // A lo plane ((x-hi)*1024)
__device__ __align__(16) unsigned d_Whp[KPP*NP];  // W plane, fp16x2 [kpair][n]
__device__ __align__(16) float d_Y[M*NP];
__device__ __align__(16) float d_g4[100*1024];    // [chpair][plane][q][2ch]
__device__ __align__(16) float d_gB0[S*H];        // [i][h]
__device__ __align__(16) float d_gB255[S*H];      // [i][h]
__device__ __align__(16) float d_poolA[M*2*H];    // zone-0 partial (relu'd)
__device__ __align__(16) float d_poolB[M*2*H];    // zone-1 partial (relu'd)
__device__ __align__(16) float d_fcW2t[L*400];    // [l][c]
__device__ __align__(16) float4 d_fcW4[100*34];   // [cquad][l] = W[l][4q..4q+3]

// ---------------- helpers ----------------
union F2U { float2 f; unsigned long long u; };
__device__ __forceinline__ float2 add2(float2 a, float2 b) {
    F2U ua, ub, uc;
    ua.f = a; ub.f = b;
    asm("add.rn.f32x2 %0, %1, %2;" : "=l"(uc.u) : "l"(ua.u), "l"(ub.u));
    return uc.f;
}
__device__ __forceinline__ float2 max2(float2 a, float2 b) {
    return make_float2(fmaxf(a.x, b.x), fmaxf(a.y, b.y));
}
__device__ __forceinline__ float4 max44(float4 a, float4 b) {
    return make_float4(fmaxf(a.x, b.x), fmaxf(a.y, b.y), fmaxf(a.z, b.z), fmaxf(a.w, b.w));
}
__device__ __forceinline__ unsigned pk2h(float a, float b) {
    __half2 t = __floats2half2_rn(a, b);
    return *reinterpret_cast<unsigned*>(&t);
}
__device__ __forceinline__ void mma_fp16(float* d, const unsigned* a, const unsigned* b) {
    asm volatile("mma.sync.aligned.m16n8k16.row.col.f32.f16.f16.f32 "
        "{%0,%1,%2,%3},{%4,%5,%6,%7},{%8,%9},{%0,%1,%2,%3};\n"
        : "+f"(d[0]), "+f"(d[1]), "+f"(d[2]), "+f"(d[3])
        : "r"(a[0]), "r"(a[1]), "r"(a[2]), "r"(a[3]), "r"(b[0]), "r"(b[1]));
}
__device__ __forceinline__ void cpa16(unsigned dst, const void* src) {
    asm volatile("cp.async.ca.shared.global [%0], [%1], 16;\n" :: "r"(dst), "l"(src));
}

// ---------------- fused prep: gather + W plane + fcW tables + g-tables ----------------
__device__ __forceinline__ float wallv(int e, int c, const float* conv_W, const float* fc_W) {
    if (e >= E) return 0.0f;
    if (c < 600) {
        int k = c / 200, h = c % 200;
        return conv_W[h*((E+P)*3) + e*3 + k];
    }
    if (c < 702) {
        int cc = c - 600, k = cc / L, l = cc % L;
        return fc_W[l*FCK + 2*H + k*E + e];
    }
    return 0.0f;
}

__global__ __launch_bounds__(256) void prep_kernel(const int* in32, const float* word_emb,
                                                   const float* conv_W, const float* fc_W,
                                                   const float* pf_emb) {
    int blk = blockIdx.x;
    int tid = threadIdx.x;
    if (blk < 2048) {                              // gather embeddings, fp16 hi/lo planes
        int row = blk;
        int lane = tid & 31;
        int hw = in32[2*lane + 1];
        unsigned nz = __ballot_sync(0xffffffffu, hw != 0);
        long long tok = (nz == 0) ? ((const long long*)in32)[row]
                                  : (long long)in32[row];
        int p = tid;
        if (p >= KPP) return;
        const float* src = word_emb + tok * E;
        float x0 = 0.0f, x1 = 0.0f;
        int e = 2*p;
        if (e < E) {
            x0 = src[e];
            x1 = (e + 1 < E) ? src[e+1] : 0.0f;
        }
        float h0 = __half2float(__float2half_rn(x0));
        float h1 = __half2float(__float2half_rn(x1));
        d_Ahp[row*KPP + p] = pk2h(h0, h1);
        d_Alp[row*KPP + p] = pk2h((x0 - h0) * 1024.0f, (x1 - h1) * 1024.0f);
        return;
    }
    if (blk < 2208) {                              // W plane, kpair = blk-2048
        int kp = blk - 2048;
        for (int c = tid; c < NP; c += 256) {
            float v0 = wallv(2*kp,     c, conv_W, fc_W);
            float v1 = wallv(2*kp + 1, c, conv_W, fc_W);
            d_Whp[kp*NP + c] = pk2h(v0, v1);
        }
        return;
    }
    if (blk == 2208) {                             // fcW2t[l][c] + fcW4[q][l]
        for (int idx = tid; idx < L*400; idx += 256) {
            int l = idx / 400, c = idx % 400;
            d_fcW2t[idx] = fc_W[l*FCK + c];
        }
        for (int idx = tid; idx < 100*34; idx += 256) {
            int q = idx / 34, l = idx % 34;
            const float* wr = fc_W + l*FCK + 4*q;
            d_fcW4[idx] = make_float4(wr[0], wr[1], wr[2], wr[3]);
        }
        return;
    }
    int h = blk - 2209;                            // 0..199 g-tables
    float w0[P], w1[P], w2[P];
    #pragma unroll
    for (int p = 0; p < P; p++) {
        const float* wp = conv_W + h*(E+P)*3 + (E+p)*3;
        w0[p] = wp[0]; w1[p] = wp[1]; w2[p] = wp[2];
    }
    for (int dd = tid; dd < 512; dd += 256) {
        int d = dd - 256;
        int i0 = abs(d-1); if (i0 > 255) i0 = 255;
        int i1 = abs(d);   if (i1 > 255) i1 = 255;
        int i2 = abs(d+1); if (i2 > 255) i2 = 255;
        float acc = 0.0f;
        #pragma unroll
        for (int p = 0; p < P; p++)
            acc += w0[p]*pf_emb[i0*P+p] + w1[p]*pf_emb[i1*P+p] + w2[p]*pf_emb[i2*P+p];
        // pair-granular layout: [chpair = h>>1][plane = dd&3][q = dd>>2][h&1]
        d_g4[(h>>1)*1024 + (dd&3)*256 + (dd>>2)*2 + (h&1)] = acc;
    }
    if (tid >= 1 && tid <= 254) {
        int i = tid;
        float a0 = 0.0f, a255 = 0.0f;
        #pragma unroll
        for (int p = 0; p < P; p++) {
            a0   += w1[p]*pf_emb[i*P+p] + w2[p]*pf_emb[(i-1)*P+p];
            a255 += w0[p]*pf_emb[(254-i >= 0 ? 254-i : i-254)*P+p] + w1[p]*pf_emb[(255-i)*P+p];
        }
        d_gB0[i*H + h]   = a0;
        d_gB255[i*H + h] = a255;
    }
}

// ---------------- GEMM: 64x64 tiles, fp16 2-pass, cp.async double-buffered ----------------
__global__ __launch_bounds__(256) void gemm_kernel() {
    __shared__ unsigned Ah[2][64][20], Al[2][64][20];
    __shared__ unsigned Bs[2][16][72];

    const int t = threadIdx.x, lane = t & 31, warp = t >> 5;
    const int wm = warp >> 1, wn = warp & 1;
    const int mBase = wm * 16, nBase = wn * 32;
    const int r0 = lane >> 2, c0 = lane & 3;

    float acch[4][4], accl[4][4];
    #pragma unroll
    for (int ni = 0; ni < 4; ni++)
        #pragma unroll
        for (int q = 0; q < 4; q++) { acch[ni][q] = 0.0f; accl[ni][q] = 0.0f; }

    const unsigned* Agh = d_Ahp + (size_t)blockIdx.x * 64 * KPP;
    const unsigned* Agl = d_Alp + (size_t)blockIdx.x * 64 * KPP;
    const unsigned* Bg  = d_Whp + blockIdx.y * 64;

    const int am   = t >> 2;
    const int aseg = (t & 3) * 4;
    const int bk   = t >> 4;
    const int bn4  = (t & 15) * 4;

    unsigned sAh = (unsigned)__cvta_generic_to_shared(&Ah[0][am][aseg]);
    unsigned sAl = (unsigned)__cvta_generic_to_shared(&Al[0][am][aseg]);
    unsigned sB  = (unsigned)__cvta_generic_to_shared(&Bs[0][bk][bn4]);
    const unsigned A_ST = 64*20*4;
    const unsigned B_ST = 16*72*4;

    {
        cpa16(sAh, Agh + am*KPP + aseg);
        cpa16(sAl, Agl + am*KPP + aseg);
        cpa16(sB,  Bg + bk*NP + bn4);
        asm volatile("cp.async.commit_group;\n");
    }

    #pragma unroll 1
    for (int ch = 0; ch < 10; ch++) {
        int st = ch & 1;
        if (ch < 9) {
            int kc = (ch + 1) * 16;
            int st1 = st ^ 1;
            cpa16(sAh + st1*A_ST, Agh + am*KPP + kc + aseg);
            cpa16(sAl + st1*A_ST, Agl + am*KPP + kc + aseg);
            cpa16(sB  + st1*B_ST, Bg + (kc + bk)*NP + bn4);
            asm volatile("cp.async.commit_group;\n");
            asm volatile("cp.async.wait_group 1;\n");
        } else {
            asm volatile("cp.async.wait_group 0;\n");
        }
        __syncthreads();

        #pragma unroll
        for (int ks = 0; ks < 2; ks++) {
            int p0 = ks*8 + c0;
            int mr = mBase + r0;
            unsigned ah[4], al[4];
            ah[0] = Ah[st][mr][p0];     al[0] = Al[st][mr][p0];
            ah[1] = Ah[st][mr+8][p0];   al[1] = Al[st][mr+8][p0];
            ah[2] = Ah[st][mr][p0+4];   al[2] = Al[st][mr][p0+4];
            ah[3] = Ah[st][mr+8][p0+4]; al[3] = Al[st][mr+8][p0+4];
            unsigned bb[4][2];
            #pragma unroll
            for (int ni = 0; ni < 4; ni++) {
                int n = nBase + ni*8 + r0;
                bb[ni][0] = Bs[st][p0][n];
                bb[ni][1] = Bs[st][p0+4][n];
            }
            #pragma unroll
            for (int ni = 0; ni < 4; ni++) {
                mma_fp16(acch[ni], ah, bb[ni]);
                mma_fp16(accl[ni], al, bb[ni]);
            }
        }
        __syncthreads();
    }

    const float RS = 1.0f / 1024.0f;
    float* Yg = d_Y + (size_t)(blockIdx.x*64)*NP + blockIdx.y*64;
    int mr = mBase + r0;
    #pragma unroll
    for (int ni = 0; ni < 4; ni++) {
        int nc = nBase + ni*8 + 2*c0;
        *(float2*)(Yg + mr*NP + nc) =
            make_float2(fmaf(accl[ni][0], RS, acch[ni][0]), fmaf(accl[ni][1], RS, acch[ni][1]));
        *(float2*)(Yg + (mr+8)*NP + nc) =
            make_float2(fmaf(accl[ni][2], RS, acch[ni][2]), fmaf(accl[ni][3], RS, acch[ni][3]));
    }
}

// ---------------- fused ct + pooling: 4 centers x 2 ch/thread, pipelined window ----------------
__device__ __forceinline__ float2 compute_ct2(int b, int j, int cb, float2 v) {
    int row = b*S + j;
    v = add2(v, *(const float2*)&d_Y[row*NP + 200 + cb]);
    if (j > 0)   v = add2(v, *(const float2*)&d_Y[(row-1)*NP + cb]);
    if (j < S-1) v = add2(v, *(const float2*)&d_Y[(row+1)*NP + 400 + cb]);
    return v;
}

#define UPD_MIX(cc, vA, vB, vC, vD, jj) do { \
    int t4_ = (jj) - 4*lt; \
    float2 x_; \
    x_ = add2(cc, vA); if (t4_ <= 0) mL[0] = max2(mL[0], x_); else mR[0] = max2(mR[0], x_); \
    x_ = add2(cc, vB); if (t4_ <= 1) mL[1] = max2(mL[1], x_); else mR[1] = max2(mR[1], x_); \
    x_ = add2(cc, vC); if (t4_ <= 2) mL[2] = max2(mL[2], x_); else mR[2] = max2(mR[2], x_); \
    x_ = add2(cc, vD); if (t4_ <= 3) mL[3] = max2(mL[3], x_); else mR[3] = max2(mR[3], x_); \
} while(0)

#define UPD_UNI(cc, vA, vB, vC, vD) do { \
    mU[0] = max2(mU[0], add2(cc, vA)); \
    mU[1] = max2(mU[1], add2(cc, vB)); \
    mU[2] = max2(mU[2], add2(cc, vC)); \
    mU[3] = max2(mU[3], add2(cc, vD)); \
} while(0)

__global__ __launch_bounds__(128) void pool_kernel(const float* conv_b) {
    int bx = blockIdx.x;            // channel quad 0..49 (2 pairs per block)
    int b  = blockIdx.y;
    int z  = blockIdx.z;            // j-zone
    __shared__ float2 gp[2][4][128];   // [group][plane][q]
    __shared__ float2 cts[2][128];
    int t = threadIdx.x, g = t >> 6, lt = t & 63;
    int pairIdx = bx*2 + g;         // 0..99
    int cb = pairIdx*2;             // channel base (2 ch)

    const float2* gsrc = (const float2*)d_g4 + pairIdx*512;
    float2* gdst = &gp[g][0][0];
    #pragma unroll
    for (int r = 0; r < 8; r++)
        gdst[lt + 64*r] = gsrc[lt + 64*r];

    float2 cb2 = *(const float2*)&conv_b[cb];
    cts[g][lt]      = compute_ct2(b, z*128 + lt, cb, cb2);
    cts[g][lt + 64] = compute_ct2(b, z*128 + lt + 64, cb, cb2);
    __syncthreads();

    const int ifirst = 4*lt + 1;
    const float NEG = -1e30f;
    float2 neg2 = make_float2(NEG, NEG);
    float2 mL[4], mR[4];
    if (z == 0) {
        float2 c0 = cts[g][0];
        #pragma unroll
        for (int k = 0; k < 4; k++) {
            int ie = min(ifirst + k, 254);
            mL[k] = add2(c0, *(const float2*)&d_gB0[ie*H + cb]);
            mR[k] = neg2;
        }
    } else {
        float2 c255 = cts[g][127];
        #pragma unroll
        for (int k = 0; k < 4; k++) {
            int ie = min(ifirst + k, 254);
            mR[k] = add2(c255, *(const float2*)&d_gB255[ie*H + cb]);
            mL[k] = neg2;
        }
    }

    const int jstart = z ? 128 : 1;
    const float2* cz = &cts[g][0] - z*128;

#define GLD(dd) gp[g][(dd)&3][(dd)>>2]
    // window invariant: v_m = g(d0+m), d0 = j + 252 - 4lt; center k at step s uses v_{s+3-k}
    int d0 = jstart + 252 - 4*lt;
    float2 v0 = GLD(d0),   v1 = GLD(d0+1), v2 = GLD(d0+2), v3 = GLD(d0+3);
    float2 v4 = GLD(d0+4), v5 = GLD(d0+5), v6 = GLD(d0+6);

    bool mixed = z ? (lt >= 32) : (lt < 32);
    int j = jstart;
    if (mixed) {
        #pragma unroll 2
        for (int blkI = 0; blkI < 31; blkI++, j += 4) {
            int dp = j + 259 - 4*lt;             // prefetch d0+7..d0+10 (next block)
            float2 p0 = GLD(dp), p1 = GLD(dp+1), p2 = GLD(dp+2), p3 = GLD(dp+3);
            float2 c0 = cz[j], c1 = cz[j+1], c2 = cz[j+2], c3 = cz[j+3];
            UPD_MIX(c0, v3, v2, v1, v0, j);
            UPD_MIX(c1, v4, v3, v2, v1, j+1);
            UPD_MIX(c2, v5, v4, v3, v2, j+2);
            UPD_MIX(c3, v6, v5, v4, v3, j+3);
            v0 = v4; v1 = v5; v2 = v6; v3 = p0; v4 = p1; v5 = p2; v6 = p3;
        }
        float2 c0 = cz[j], c1 = cz[j+1], c2 = cz[j+2];
        UPD_MIX(c0, v3, v2, v1, v0, j);
        UPD_MIX(c1, v4, v3, v2, v1, j+1);
        UPD_MIX(c2, v5, v4, v3, v2, j+2);
    } else {
        float2 mU[4];
        #pragma unroll
        for (int k = 0; k < 4; k++) mU[k] = z ? mR[k] : mL[k];
        #pragma unroll 2
        for (int blkI = 0; blkI < 31; blkI++, j += 4) {
            int dp = j + 259 - 4*lt;
            float2 p0 = GLD(dp), p1 = GLD(dp+1), p2 = GLD(dp+2), p3 = GLD(dp+3);
            float2 c0 = cz[j], c1 = cz[j+1], c2 = cz[j+2], c3 = cz[j+3];
            UPD_UNI(c0, v3, v2, v1, v0);
            UPD_UNI(c1, v4, v3, v2, v1);
            UPD_UNI(c2, v5, v4, v3, v2);
            UPD_UNI(c3, v6, v5, v4, v3);
            v0 = v4; v1 = v5; v2 = v6; v3 = p0; v4 = p1; v5 = p2; v6 = p3;
        }
        float2 c0 = cz[j], c1 = cz[j+1], c2 = cz[j+2];
        UPD_UNI(c0, v3, v2, v1, v0);
        UPD_UNI(c1, v4, v3, v2, v1);
        UPD_UNI(c2, v5, v4, v3, v2);
        #pragma unroll
        for (int k = 0; k < 4; k++) { if (z) mR[k] = mU[k]; else mL[k] = mU[k]; }
    }
#undef GLD

    float2 z2 = make_float2(0.f, 0.f);
    float* dst = z ? d_poolB : d_poolA;
    #pragma unroll
    for (int k = 0; k < 4; k++) {
        int i = ifirst + k;
        if (i <= 254) {
            *(float2*)&dst[(b*S + i)*(2*H) + cb]     = max2(mL[k], z2);
            *(float2*)&dst[(b*S + i)*(2*H) + H + cb] = max2(mR[k], z2);
        }
    }
}

// ---------------- final logits: 512 thr, 2 warps/row split-q, manual 5-wide MLP ----------------
__global__ __launch_bounds__(512) void final_kernel(const float* fc_b, float* out) {
    __shared__ float4 s_pm[8][100];     // 8 rows x 400 ch, relu'd pool maxes
    __shared__ float s_part[16][32];
    __shared__ float s_p32[16], s_p33[16];
    int tid = threadIdx.x;
    int gw0 = blockIdx.x * 8;

    // cooperative staged load: coalesced, deep MLP by construction
    const float4* pA = (const float4*)d_poolA + gw0*100;
    const float4* pB = (const float4*)d_poolB + gw0*100;
    #pragma unroll
    for (int it = 0; it < 2; it++) {
        int idx = tid + it*512;
        if (idx < 800)
            s_pm[idx/100][idx%100] = max44(pA[idx], pB[idx]);
    }
    __syncthreads();

    int w = tid >> 5, lane = tid & 31;
    int r = w & 7, half = w >> 3;
    const float4* Wq = d_fcW4 + lane;   // lane-major: 4 lines/warp/load, L1-hot
    const float4* mrow = &s_pm[r][0];
    const int qb = half * 50;

    float a0 = 0.f, a1 = 0.f, a2 = 0.f, a3 = 0.f;
    #pragma unroll 2
    for (int qq = 0; qq < 50; qq += 5) {
        int q = qb + qq;
        float4 wv0 = Wq[(q+0)*34], wv1 = Wq[(q+1)*34], wv2 = Wq[(q+2)*34],
               wv3 = Wq[(q+3)*34], wv4 = Wq[(q+4)*34];
        float4 m0 = mrow[q+0], m1 = mrow[q+1], m2 = mrow[q+2],
               m3 = mrow[q+3], m4 = mrow[q+4];
        a0 += m0.x*wv0.x + m1.x*wv1.x + m2.x*wv2.x + m3.x*wv3.x + m4.x*wv4.x;
        a1 += m0.y*wv0.y + m1.y*wv1.y + m2.y*wv2.y + m3.y*wv3.y + m4.y*wv4.y;
        a2 += m0.z*wv0.z + m1.z*wv1.z + m2.z*wv2.z + m3.z*wv3.z + m4.z*wv4.z;
        a3 += m0.w*wv0.w + m1.w*wv1.w + m2.w*wv2.w + m3.w*wv3.w + m4.w*wv4.w;
    }
    s_part[w][lane] = (a0 + a1) + (a2 + a3);

    const float* spm = (const float*)mrow;
    const float* W32 = d_fcW2t + 32 * 400;
    const float* W33 = d_fcW2t + 33 * 400;
    float r32 = 0.f, r33 = 0.f;
    int cend = half*200 + 200;
    #pragma unroll
    for (int c = half*200 + lane; c < cend; c += 32) {
        float p = spm[c];
        r32 += p * W32[c];
        r33 += p * W33[c];
    }
    #pragma unroll
    for (int off = 16; off > 0; off >>= 1) {
        r32 += __shfl_xor_sync(0xFFFFFFFF, r32, off);
        r33 += __shfl_xor_sync(0xFFFFFFFF, r33, off);
    }
    if (lane == 0) { s_p32[w] = r32; s_p33[w] = r33; }
    __syncthreads();

    if (w >= 8) return;
    int gw = gw0 + r;
    int s = gw & (S-1);
    float* o = out + gw * L;
    if (s == 0 || s == S-1) {
        o[lane] = 0.0f;
        if (lane < 2) o[lane + 32] = (lane == 1) ? 1.0f : 0.0f;
        return;
    }
    float acc0 = s_part[w][lane] + s_part[w+8][lane] + fc_b[lane];
    acc0 += d_Y[(gw-1)*NP + 600 + lane]
          + d_Y[gw*NP     + 634 + lane]
          + d_Y[(gw+1)*NP + 668 + lane];
    o[lane] = acc0;

    if (lane < 2) {
        float rr = (lane == 0) ? (s_p32[w] + s_p32[w+8]) : (s_p33[w] + s_p33[w+8]);
        rr += fc_b[32 + lane]
            + d_Y[(gw-1)*NP + 632 + lane]
            + d_Y[gw*NP     + 666 + lane]
            + d_Y[(gw+1)*NP + 700 + lane];
        o[32 + lane] = rr;
    }
}

extern "C" void kernel_launch(void* const* d_in, const int* in_sizes, int n_in,
                              void* d_out, int out_size) {
    const int*   inputs   = (const int*)d_in[0];
    const float* word_emb = (const float*)d_in[1];
    const float* pf_emb   = (const float*)d_in[2];
    const float* conv_W   = (const float*)d_in[3];
    const float* conv_b   = (const float*)d_in[4];
    const float* fc_W     = (const float*)d_in[5];
    const float* fc_b     = (const float*)d_in[6];
    float* out = (float*)d_out;

    prep_kernel<<<2409, 256>>>(inputs, word_emb, conv_W, fc_W, pf_emb);   // launch 0

    dim3 ggrid(M/64, NP/64);
    gemm_kernel<<<ggrid, 256>>>();                        // launch 1

    dim3 pgrid(50, B, 2);
    pool_kernel<<<pgrid, 128>>>(conv_b);                  // launch 2

    final_kernel<<<256, 512>>>(fc_b, out);                // launch 3 (profiled slot)
}

// round 17
// speedup vs baseline: 1.0409x; 1.0038x over previous
#include <cuda_runtime.h>
#include <cuda_fp16.h>

#define E   300
#define P   5
#define H   200
#define S   256
#define L   34
#define B   8
#define KPP 160          // k-word-pairs per A row (K = 320 padded)
#define NP  704          // N padded (702 -> 704)
#define M   (B*S)        // 2048
#define FCK (3*E + 2*H)  // 1300

// ---------------- scratch ----------------
__device__ __align__(16) unsigned d_Ahp[M*KPP];   // A hi plane, fp16x2 [row][kpair]
__device__ __align__(16) unsigned d_Alp[M*KPP];   // A lo plane ((x-hi)*1024)
__device__ __align__(16) unsigned d_Whp[KPP*NP];  // W plane, fp16x2 [kpair][n]
__device__ __align__(16) float d_Y[M*NP];
__device__ __align__(16) float d_g4[50*2048];     // [cquad][plane][q][4ch]
__device__ __align__(16) float d_gB0[S*H];        // [i][h]
__device__ __align__(16) float d_gB255[S*H];      // [i][h]
__device__ __align__(16) float d_poolA[M*2*H];    // zone-0 partial (relu'd)
__device__ __align__(16) float d_poolB[M*2*H];    // zone-1 partial (relu'd)
__device__ __align__(16) float d_poolC[M*2*H];    // zone-2 partial (relu'd)
__device__ __align__(16) float d_fcW2t[L*400];    // [l][c]
__device__ __align__(16) float4 d_fcW4[100*34];   // [cquad][l] = W[l][4q..4q+3]

// ---------------- helpers ----------------
union F2U { float2 f; unsigned long long u; };
__device__ __forceinline__ float2 add2(float2 a, float2 b) {
    F2U ua, ub, uc;
    ua.f = a; ub.f = b;
    asm("add.rn.f32x2 %0, %1, %2;" : "=l"(uc.u) : "l"(ua.u), "l"(ub.u));
    return uc.f;
}
__device__ __forceinline__ float4 add44(float4 a, float4 b) {
    float2 lo = add2(make_float2(a.x, a.y), make_float2(b.x, b.y));
    float2 hi = add2(make_float2(a.z, a.w), make_float2(b.z, b.w));
    return make_float4(lo.x, lo.y, hi.x, hi.y);
}
__device__ __forceinline__ float4 max44(float4 a, float4 b) {
    return make_float4(fmaxf(a.x, b.x), fmaxf(a.y, b.y), fmaxf(a.z, b.z), fmaxf(a.w, b.w));
}
__device__ __forceinline__ unsigned pk2h(float a, float b) {
    __half2 t = __floats2half2_rn(a, b);
    return *reinterpret_cast<unsigned*>(&t);
}
__device__ __forceinline__ void mma_fp16(float* d, const unsigned* a, const unsigned* b) {
    asm volatile("mma.sync.aligned.m16n8k16.row.col.f32.f16.f16.f32 "
        "{%0,%1,%2,%3},{%4,%5,%6,%7},{%8,%9},{%0,%1,%2,%3};\n"
        : "+f"(d[0]), "+f"(d[1]), "+f"(d[2]), "+f"(d[3])
        : "r"(a[0]), "r"(a[1]), "r"(a[2]), "r"(a[3]), "r"(b[0]), "r"(b[1]));
}
__device__ __forceinline__ void cpa16(unsigned dst, const void* src) {
    asm volatile("cp.async.ca.shared.global [%0], [%1], 16;\n" :: "r"(dst), "l"(src));
}

// ---------------- fused prep: gather + W plane + fcW tables + g-tables ----------------
__device__ __forceinline__ float wallv(int e, int c, const float* conv_W, const float* fc_W) {
    if (e >= E) return 0.0f;
    if (c < 600) {
        int k = c / 200, h = c % 200;
        return conv_W[h*((E+P)*3) + e*3 + k];
    }
    if (c < 702) {
        int cc = c - 600, k = cc / L, l = cc % L;
        return fc_W[l*FCK + 2*H + k*E + e];
    }
    return 0.0f;
}

__global__ __launch_bounds__(256) void prep_kernel(const int* in32, const float* word_emb,
                                                   const float* conv_W, const float* fc_W,
                                                   const float* pf_emb) {
    int blk = blockIdx.x;
    int tid = threadIdx.x;
    if (blk < 2048) {                              // gather embeddings, fp16 hi/lo planes
        int row = blk;
        int lane = tid & 31;
        int hw = in32[2*lane + 1];
        unsigned nz = __ballot_sync(0xffffffffu, hw != 0);
        long long tok = (nz == 0) ? ((const long long*)in32)[row]
                                  : (long long)in32[row];
        int p = tid;
        if (p >= KPP) return;
        const float* src = word_emb + tok * E;
        float x0 = 0.0f, x1 = 0.0f;
        int e = 2*p;
        if (e < E) {
            x0 = src[e];
            x1 = (e + 1 < E) ? src[e+1] : 0.0f;
        }
        float h0 = __half2float(__float2half_rn(x0));
        float h1 = __half2float(__float2half_rn(x1));
        d_Ahp[row*KPP + p] = pk2h(h0, h1);
        d_Alp[row*KPP + p] = pk2h((x0 - h0) * 1024.0f, (x1 - h1) * 1024.0f);
        return;
    }
    if (blk < 2208) {                              // W plane, kpair = blk-2048
        int kp = blk - 2048;
        for (int c = tid; c < NP; c += 256) {
            float v0 = wallv(2*kp,     c, conv_W, fc_W);
            float v1 = wallv(2*kp + 1, c, conv_W, fc_W);
            d_Whp[kp*NP + c] = pk2h(v0, v1);
        }
        return;
    }
    if (blk == 2208) {                             // fcW2t[l][c] + fcW4[q][l]
        for (int idx = tid; idx < L*400; idx += 256) {
            int l = idx / 400, c = idx % 400;
            d_fcW2t[idx] = fc_W[l*FCK + c];
        }
        for (int idx = tid; idx < 100*34; idx += 256) {
            int q = idx / 34, l = idx % 34;
            const float* wr = fc_W + l*FCK + 4*q;
            d_fcW4[idx] = make_float4(wr[0], wr[1], wr[2], wr[3]);
        }
        return;
    }
    int h = blk - 2209;                            // 0..199 g-tables
    float w0[P], w1[P], w2[P];
    #pragma unroll
    for (int p = 0; p < P; p++) {
        const float* wp = conv_W + h*(E+P)*3 + (E+p)*3;
        w0[p] = wp[0]; w1[p] = wp[1]; w2[p] = wp[2];
    }
    for (int dd = tid; dd < 512; dd += 256) {
        int d = dd - 256;
        int i0 = abs(d-1); if (i0 > 255) i0 = 255;
        int i1 = abs(d);   if (i1 > 255) i1 = 255;
        int i2 = abs(d+1); if (i2 > 255) i2 = 255;
        float acc = 0.0f;
        #pragma unroll
        for (int p = 0; p < P; p++)
            acc += w0[p]*pf_emb[i0*P+p] + w1[p]*pf_emb[i1*P+p] + w2[p]*pf_emb[i2*P+p];
        d_g4[(h>>2)*2048 + (dd&3)*512 + (dd>>2)*4 + (h&3)] = acc;
    }
    if (tid >= 1 && tid <= 254) {
        int i = tid;
        float a0 = 0.0f, a255 = 0.0f;
        #pragma unroll
        for (int p = 0; p < P; p++) {
            a0   += w1[p]*pf_emb[i*P+p] + w2[p]*pf_emb[(i-1)*P+p];
            a255 += w0[p]*pf_emb[(254-i >= 0 ? 254-i : i-254)*P+p] + w1[p]*pf_emb[(255-i)*P+p];
        }
        d_gB0[i*H + h]   = a0;
        d_gB255[i*H + h] = a255;
    }
}

// ---------------- GEMM: 64x64 tiles, fp16 2-pass, cp.async double-buffered ----------------
__global__ __launch_bounds__(256) void gemm_kernel() {
    __shared__ unsigned Ah[2][64][20], Al[2][64][20];
    __shared__ unsigned Bs[2][16][72];

    const int t = threadIdx.x, lane = t & 31, warp = t >> 5;
    const int wm = warp >> 1, wn = warp & 1;
    const int mBase = wm * 16, nBase = wn * 32;
    const int r0 = lane >> 2, c0 = lane & 3;

    float acch[4][4], accl[4][4];
    #pragma unroll
    for (int ni = 0; ni < 4; ni++)
        #pragma unroll
        for (int q = 0; q < 4; q++) { acch[ni][q] = 0.0f; accl[ni][q] = 0.0f; }

    const unsigned* Agh = d_Ahp + (size_t)blockIdx.x * 64 * KPP;
    const unsigned* Agl = d_Alp + (size_t)blockIdx.x * 64 * KPP;
    const unsigned* Bg  = d_Whp + blockIdx.y * 64;

    const int am   = t >> 2;
    const int aseg = (t & 3) * 4;
    const int bk   = t >> 4;
    const int bn4  = (t & 15) * 4;

    unsigned sAh = (unsigned)__cvta_generic_to_shared(&Ah[0][am][aseg]);
    unsigned sAl = (unsigned)__cvta_generic_to_shared(&Al[0][am][aseg]);
    unsigned sB  = (unsigned)__cvta_generic_to_shared(&Bs[0][bk][bn4]);
    const unsigned A_ST = 64*20*4;
    const unsigned B_ST = 16*72*4;

    {
        cpa16(sAh, Agh + am*KPP + aseg);
        cpa16(sAl, Agl + am*KPP + aseg);
        cpa16(sB,  Bg + bk*NP + bn4);
        asm volatile("cp.async.commit_group;\n");
    }

    #pragma unroll 1
    for (int ch = 0; ch < 10; ch++) {
        int st = ch & 1;
        if (ch < 9) {
            int kc = (ch + 1) * 16;
            int st1 = st ^ 1;
            cpa16(sAh + st1*A_ST, Agh + am*KPP + kc + aseg);
            cpa16(sAl + st1*A_ST, Agl + am*KPP + kc + aseg);
            cpa16(sB  + st1*B_ST, Bg + (kc + bk)*NP + bn4);
            asm volatile("cp.async.commit_group;\n");
            asm volatile("cp.async.wait_group 1;\n");
        } else {
            asm volatile("cp.async.wait_group 0;\n");
        }
        __syncthreads();

        #pragma unroll
        for (int ks = 0; ks < 2; ks++) {
            int p0 = ks*8 + c0;
            int mr = mBase + r0;
            unsigned ah[4], al[4];
            ah[0] = Ah[st][mr][p0];     al[0] = Al[st][mr][p0];
            ah[1] = Ah[st][mr+8][p0];   al[1] = Al[st][mr+8][p0];
            ah[2] = Ah[st][mr][p0+4];   al[2] = Al[st][mr][p0+4];
            ah[3] = Ah[st][mr+8][p0+4]; al[3] = Al[st][mr+8][p0+4];
            unsigned bb[4][2];
            #pragma unroll
            for (int ni = 0; ni < 4; ni++) {
                int n = nBase + ni*8 + r0;
                bb[ni][0] = Bs[st][p0][n];
                bb[ni][1] = Bs[st][p0+4][n];
            }
            #pragma unroll
            for (int ni = 0; ni < 4; ni++) {
                mma_fp16(acch[ni], ah, bb[ni]);
                mma_fp16(accl[ni], al, bb[ni]);
            }
        }
        __syncthreads();
    }

    const float RS = 1.0f / 1024.0f;
    float* Yg = d_Y + (size_t)(blockIdx.x*64)*NP + blockIdx.y*64;
    int mr = mBase + r0;
    #pragma unroll
    for (int ni = 0; ni < 4; ni++) {
        int nc = nBase + ni*8 + 2*c0;
        *(float2*)(Yg + mr*NP + nc) =
            make_float2(fmaf(accl[ni][0], RS, acch[ni][0]), fmaf(accl[ni][1], RS, acch[ni][1]));
        *(float2*)(Yg + (mr+8)*NP + nc) =
            make_float2(fmaf(accl[ni][2], RS, acch[ni][2]), fmaf(accl[ni][3], RS, acch[ni][3]));
    }
}

// ---------------- fused ct + pooling: 4 centers x 4 ch/thread, 3 j-zones ----------------
__device__ __forceinline__ float4 compute_ct4(int b, int j, int cb, float4 v) {
    int row = b*S + j;
    v = add44(v, *(const float4*)&d_Y[row*NP + 200 + cb]);
    if (j > 0)   v = add44(v, *(const float4*)&d_Y[(row-1)*NP + cb]);
    if (j < S-1) v = add44(v, *(const float4*)&d_Y[(row+1)*NP + 400 + cb]);
    return v;
}

#define UPD_MIX(cc, vA, vB, vC, vD, jj) do { \
    int t4_ = (jj) - 4*lt; \
    float4 x_; \
    x_ = add44(cc, vA); if (t4_ <= 0) mL[0] = max44(mL[0], x_); else mR[0] = max44(mR[0], x_); \
    x_ = add44(cc, vB); if (t4_ <= 1) mL[1] = max44(mL[1], x_); else mR[1] = max44(mR[1], x_); \
    x_ = add44(cc, vC); if (t4_ <= 2) mL[2] = max44(mL[2], x_); else mR[2] = max44(mR[2], x_); \
    x_ = add44(cc, vD); if (t4_ <= 3) mL[3] = max44(mL[3], x_); else mR[3] = max44(mR[3], x_); \
} while(0)

#define UPD_UNI(cc, vA, vB, vC, vD) do { \
    mU[0] = max44(mU[0], add44(cc, vA)); \
    mU[1] = max44(mU[1], add44(cc, vB)); \
    mU[2] = max44(mU[2], add44(cc, vC)); \
    mU[3] = max44(mU[3], add44(cc, vD)); \
} while(0)

__global__ __launch_bounds__(128, 5) void pool_kernel(const float* conv_b) {
    int bx = blockIdx.x;            // channel octet 0..24
    int b  = blockIdx.y;
    int z  = blockIdx.z;            // j-zone 0..2: [0,86) [86,171) [171,256)
    __shared__ float4 gp[2][4][88];    // [group][plane][qslot]
    __shared__ float4 cts[2][86];
    int t = threadIdx.x, g = t >> 6, lt = t & 63;
    int cb = bx*8 + g*4;

    const int zlo  = (z == 0) ? 0 : (z == 1 ? 86 : 171);
    const int zhi  = (z == 0) ? 86 : (z == 1 ? 171 : 256);
    const int qoff = (z == 0) ? 0 : (z == 1 ? 21 : 42);
    const int jstart = (z == 0) ? 1 : zlo;
    const int jend   = (z == 2) ? 254 : (zhi - 1);

    // fill g planes for this zone's dd window (qoff .. qoff+87, clamped)
    const float4* gsrc = (const float4*)d_g4 + (bx*2 + g)*512;
    #pragma unroll
    for (int p = 0; p < 4; p++) {
        gp[g][p][lt] = gsrc[p*128 + min(qoff + lt, 127)];
        if (lt < 24) gp[g][p][lt + 64] = gsrc[p*128 + min(qoff + lt + 64, 127)];
    }
    float4 cb4 = *(const float4*)&conv_b[cb];
    int lenz = zhi - zlo;
    cts[g][lt] = compute_ct4(b, zlo + lt, cb, cb4);
    if (lt + 64 < lenz) cts[g][lt + 64] = compute_ct4(b, zlo + lt + 64, cb, cb4);
    __syncthreads();

    const int ifirst = 4*lt + 1;
    const float NEG = -1e30f;
    float4 neg4 = make_float4(NEG, NEG, NEG, NEG);
    float4 mL[4], mR[4];
    #pragma unroll
    for (int k = 0; k < 4; k++) { mL[k] = neg4; mR[k] = neg4; }
    if (z == 0) {
        float4 c0 = cts[g][0];                  // j = 0
        #pragma unroll
        for (int k = 0; k < 4; k++) {
            int ie = min(ifirst + k, 254);
            mL[k] = add44(c0, *(const float4*)&d_gB0[ie*H + cb]);
        }
    } else if (z == 2) {
        float4 c255 = cts[g][84];               // j = 255
        #pragma unroll
        for (int k = 0; k < 4; k++) {
            int ie = min(ifirst + k, 254);
            mR[k] = add44(c255, *(const float4*)&d_gB255[ie*H + cb]);
        }
    }

    const float4* cz = &cts[g][0] - zlo;

#define GLD(dd) gp[g][(dd)&3][((dd)>>2) - qoff]
    // window invariant: v_m = g(d0+m), d0 = j + 252 - 4lt; center k at step s uses v_{s+3-k}
    int d0 = jstart + 252 - 4*lt;
    float4 v0 = GLD(d0),   v1 = GLD(d0+1), v2 = GLD(d0+2), v3 = GLD(d0+3);
    float4 v4 = GLD(d0+4), v5 = GLD(d0+5), v6 = GLD(d0+6);

    // warp side classification: warp covers centers [128wi+1, 128wi+128]
    int wi = lt >> 5;
    bool allLeft  = (jend < 128*wi + 1);
    bool allRight = (jstart >= 128*wi + 128);
    int j = jstart;
    if (!allLeft && !allRight) {
        #pragma unroll 2
        for (int blkI = 0; blkI < 21; blkI++, j += 4) {
            int dp = j + 259 - 4*lt;             // prefetch d0+7..d0+10 (next block)
            float4 p0 = GLD(dp), p1 = GLD(dp+1), p2 = GLD(dp+2), p3 = GLD(dp+3);
            float4 c0 = cz[j], c1 = cz[j+1], c2 = cz[j+2], c3 = cz[j+3];
            UPD_MIX(c0, v3, v2, v1, v0, j);
            UPD_MIX(c1, v4, v3, v2, v1, j+1);
            UPD_MIX(c2, v5, v4, v3, v2, j+2);
            UPD_MIX(c3, v6, v5, v4, v3, j+3);
            v0 = v4; v1 = v5; v2 = v6; v3 = p0; v4 = p1; v5 = p2; v6 = p3;
        }
        if (j <= jend) {
            float4 c0 = cz[j];
            UPD_MIX(c0, v3, v2, v1, v0, j);
        }
    } else {
        float4 mU[4];
        #pragma unroll
        for (int k = 0; k < 4; k++) mU[k] = allRight ? mR[k] : mL[k];
        #pragma unroll 2
        for (int blkI = 0; blkI < 21; blkI++, j += 4) {
            int dp = j + 259 - 4*lt;
            float4 p0 = GLD(dp), p1 = GLD(dp+1), p2 = GLD(dp+2), p3 = GLD(dp+3);
            float4 c0 = cz[j], c1 = cz[j+1], c2 = cz[j+2], c3 = cz[j+3];
            UPD_UNI(c0, v3, v2, v1, v0);
            UPD_UNI(c1, v4, v3, v2, v1);
            UPD_UNI(c2, v5, v4, v3, v2);
            UPD_UNI(c3, v6, v5, v4, v3);
            v0 = v4; v1 = v5; v2 = v6; v3 = p0; v4 = p1; v5 = p2; v6 = p3;
        }
        if (j <= jend) {
            float4 c0 = cz[j];
            UPD_UNI(c0, v3, v2, v1, v0);
        }
        #pragma unroll
        for (int k = 0; k < 4; k++) { if (allRight) mR[k] = mU[k]; else mL[k] = mU[k]; }
    }
#undef GLD

    float4 z4 = make_float4(0.f, 0.f, 0.f, 0.f);
    float* dst = (z == 0) ? d_poolA : (z == 1 ? d_poolB : d_poolC);
    #pragma unroll
    for (int k = 0; k < 4; k++) {
        int i = ifirst + k;
        if (i <= 254) {
            *(float4*)&dst[(b*S + i)*(2*H) + cb]     = max44(mL[k], z4);
            *(float4*)&dst[(b*S + i)*(2*H) + H + cb] = max44(mR[k], z4);
        }
    }
}

// ---------------- final logits: 512 thr, 2 warps/row split-q, manual 5-wide MLP ----------------
__global__ __launch_bounds__(512) void final_kernel(const float* fc_b, float* out) {
    __shared__ float4 s_pm[8][100];     // 8 rows x 400 ch, relu'd pool maxes
    __shared__ float s_part[16][32];
    __shared__ float s_p32[16], s_p33[16];
    int tid = threadIdx.x;
    int gw0 = blockIdx.x * 8;

    const float4* pA = (const float4*)d_poolA + gw0*100;
    const float4* pB = (const float4*)d_poolB + gw0*100;
    const float4* pC = (const float4*)d_poolC + gw0*100;
    #pragma unroll
    for (int it = 0; it < 2; it++) {
        int idx = tid + it*512;
        if (idx < 800)
            s_pm[idx/100][idx%100] = max44(max44(pA[idx], pB[idx]), pC[idx]);
    }
    __syncthreads();

    int w = tid >> 5, lane = tid & 31;
    int r = w & 7, half = w >> 3;
    const float4* Wq = d_fcW4 + lane;   // lane-major: 4 lines/warp/load, L1-hot
    const float4* mrow = &s_pm[r][0];
    const int qb = half * 50;

    float a0 = 0.f, a1 = 0.f, a2 = 0.f, a3 = 0.f;
    #pragma unroll 2
    for (int qq = 0; qq < 50; qq += 5) {
        int q = qb + qq;
        float4 wv0 = Wq[(q+0)*34], wv1 = Wq[(q+1)*34], wv2 = Wq[(q+2)*34],
               wv3 = Wq[(q+3)*34], wv4 = Wq[(q+4)*34];
        float4 m0 = mrow[q+0], m1 = mrow[q+1], m2 = mrow[q+2],
               m3 = mrow[q+3], m4 = mrow[q+4];
        a0 += m0.x*wv0.x + m1.x*wv1.x + m2.x*wv2.x + m3.x*wv3.x + m4.x*wv4.x;
        a1 += m0.y*wv0.y + m1.y*wv1.y + m2.y*wv2.y + m3.y*wv3.y + m4.y*wv4.y;
        a2 += m0.z*wv0.z + m1.z*wv1.z + m2.z*wv2.z + m3.z*wv3.z + m4.z*wv4.z;
        a3 += m0.w*wv0.w + m1.w*wv1.w + m2.w*wv2.w + m3.w*wv3.w + m4.w*wv4.w;
    }
    s_part[w][lane] = (a0 + a1) + (a2 + a3);

    const float* spm = (const float*)mrow;
    const float* W32 = d_fcW2t + 32 * 400;
    const float* W33 = d_fcW2t + 33 * 400;
    float r32 = 0.f, r33 = 0.f;
    int cend = half*200 + 200;
    #pragma unroll
    for (int c = half*200 + lane; c < cend; c += 32) {
        float p = spm[c];
        r32 += p * W32[c];
        r33 += p * W33[c];
    }
    #pragma unroll
    for (int off = 16; off > 0; off >>= 1) {
        r32 += __shfl_xor_sync(0xFFFFFFFF, r32, off);
        r33 += __shfl_xor_sync(0xFFFFFFFF, r33, off);
    }
    if (lane == 0) { s_p32[w] = r32; s_p33[w] = r33; }
    __syncthreads();

    if (w >= 8) return;
    int gw = gw0 + r;
    int s = gw & (S-1);
    float* o = out + gw * L;
    if (s == 0 || s == S-1) {
        o[lane] = 0.0f;
        if (lane < 2) o[lane + 32] = (lane == 1) ? 1.0f : 0.0f;
        return;
    }
    float acc0 = s_part[w][lane] + s_part[w+8][lane] + fc_b[lane];
    acc0 += d_Y[(gw-1)*NP + 600 + lane]
          + d_Y[gw*NP     + 634 + lane]
          + d_Y[(gw+1)*NP + 668 + lane];
    o[lane] = acc0;

    if (lane < 2) {
        float rr = (lane == 0) ? (s_p32[w] + s_p32[w+8]) : (s_p33[w] + s_p33[w+8]);
        rr += fc_b[32 + lane]
            + d_Y[(gw-1)*NP + 632 + lane]
            + d_Y[gw*NP     + 666 + lane]
            + d_Y[(gw+1)*NP + 700 + lane];
        o[32 + lane] = rr;
    }
}

extern "C" void kernel_launch(void* const* d_in, const int* in_sizes, int n_in,
                              void* d_out, int out_size) {
    const int*   inputs   = (const int*)d_in[0];
    const float* word_emb = (const float*)d_in[1];
    const float* pf_emb   = (const float*)d_in[2];
    const float* conv_W   = (const float*)d_in[3];
    const float* conv_b   = (const float*)d_in[4];
    const float* fc_W     = (const float*)d_in[5];
    const float* fc_b     = (const float*)d_in[6];
    float* out = (float*)d_out;

    prep_kernel<<<2409, 256>>>(inputs, word_emb, conv_W, fc_W, pf_emb);   // launch 0

    dim3 ggrid(M/64, NP/64);
    gemm_kernel<<<ggrid, 256>>>();                        // launch 1

    dim3 pgrid(25, B, 3);
    pool_kernel<<<pgrid, 128>>>(conv_b);                  // launch 2

    final_kernel<<<256, 512>>>(fc_b, out);                // launch 3 (profiled slot)
}